// round 3
// baseline (speedup 1.0000x reference)
#include <cuda_runtime.h>
typedef unsigned long long ull;
#define BB 128
#define SS 512
#define HH 1024
#define NG 4096
#define KT 32
#define NB 128

__device__ float g_h0[2][BB * HH];
__device__ float g_h1[2][BB * HH];
__device__ float g_sp[NB][BB];
__device__ unsigned g_cnt, g_gen;

__device__ __forceinline__ void fma2(ull& a, ull x, ull y) {
    asm("fma.rn.f32x2 %0, %1, %2, %0;" : "+l"(a) : "l"(x), "l"(y));
}
__device__ __forceinline__ ull dup2(float w) {
    ull r; asm("mov.b64 %0, {%1, %1};" : "=l"(r) : "f"(w)); return r;
}

struct Smem {
    union { float Xs[KT][128]; float As[32][128]; };
    float Ws[KT][32];
    float c0s[BB][8];
    float c1s[BB][8];
    float ut[BB];
    float sred[256];
};

__global__ void init_kernel() {
    int i = blockIdx.x * blockDim.x + threadIdx.x;
    if (i < BB * HH) { g_h0[0][i] = 0.f; g_h1[0][i] = 0.f; }
    if (i == 0) { g_cnt = 0; g_gen = 0; }
}

__device__ __forceinline__ void gbar(unsigned target) {
    __syncthreads();
    if (threadIdx.x == 0) {
        __threadfence();
        if (atomicAdd(&g_cnt, 1u) == NB - 1) {
            g_cnt = 0;
            __threadfence();
            atomicAdd(&g_gen, 1u);
        } else {
            while (*(volatile unsigned*)&g_gen < target) {}
        }
        __threadfence();
    }
    __syncthreads();
}

template <int L1F>
__device__ __forceinline__ void cell(
    Smem& s, int tid, int j0, int t,
    const float* __restrict__ Xa, size_t lda, const float* __restrict__ Xb,
    const float* __restrict__ Wa, const float* __restrict__ Wb,
    const float* __restrict__ bias, float (*cs)[8],
    const float* __restrict__ hold, float* __restrict__ hnew,
    const float* __restrict__ sw, float* __restrict__ out)
{
    const int rg = tid & 15, cg = tid >> 4;
    ull acc[4][2] = {};
    for (int k0 = 0; k0 < 2048; k0 += KT) {
        const float* xs_; size_t str; const float* ws_; int kb;
        if (k0 < 1024) { xs_ = Xa; str = lda; ws_ = Wa; kb = k0; }
        else           { xs_ = Xb; str = HH;  ws_ = Wb; kb = k0 - 1024; }
#pragma unroll
        for (int it = 0; it < 4; it++) {
            int idx = it * 256 + tid;
            int b = idx & 127, kq = idx >> 7;
            float4 v = __ldcg((const float4*)(xs_ + (size_t)b * str + kb + kq * 4));
            s.Xs[kq * 4 + 0][b] = v.x;
            s.Xs[kq * 4 + 1][b] = v.y;
            s.Xs[kq * 4 + 2][b] = v.z;
            s.Xs[kq * 4 + 3][b] = v.w;
        }
#pragma unroll
        for (int it = 0; it < 4; it++) {
            int idx = it * 256 + tid;
            int kk = idx >> 5, col = idx & 31;
            int n = (col >> 3) * HH + j0 + (col & 7);
            s.Ws[kk][col] = __ldg(ws_ + (size_t)(kb + kk) * NG + n);
        }
        __syncthreads();
#pragma unroll
        for (int kk = 0; kk < KT; kk++) {
            ulonglong2 A0 = *(const ulonglong2*)&s.Xs[kk][4 * rg];
            ulonglong2 A1 = *(const ulonglong2*)&s.Xs[kk][64 + 4 * rg];
            float2 wv = *(const float2*)&s.Ws[kk][2 * cg];
            ull s0 = dup2(wv.x), s1 = dup2(wv.y);
            fma2(acc[0][0], A0.x, s0); fma2(acc[1][0], A0.y, s0);
            fma2(acc[2][0], A1.x, s0); fma2(acc[3][0], A1.y, s0);
            fma2(acc[0][1], A0.x, s1); fma2(acc[1][1], A0.y, s1);
            fma2(acc[2][1], A1.x, s1); fma2(acc[3][1], A1.y, s1);
        }
        __syncthreads();
    }
#pragma unroll
    for (int c = 0; c < 2; c++) {
        *(ull*)&s.As[2 * cg + c][4 * rg]      = acc[0][c];
        *(ull*)&s.As[2 * cg + c][4 * rg + 2]  = acc[1][c];
        *(ull*)&s.As[2 * cg + c][64 + 4 * rg]     = acc[2][c];
        *(ull*)&s.As[2 * cg + c][64 + 4 * rg + 2] = acc[3][c];
    }
    __syncthreads();
    float sp = 0.f;
#pragma unroll
    for (int it = 0; it < 4; it++) {
        int e = it * 256 + tid;
        int b = e & 127, jj = e >> 7;
        int j = j0 + jj;
        float ai = s.As[jj][b]      + bias[j];
        float af = s.As[8 + jj][b]  + bias[HH + j];
        float ag = s.As[16 + jj][b] + bias[2 * HH + j];
        float ao = s.As[24 + jj][b] + bias[3 * HH + j];
        float ig = 1.f / (1.f + expf(-ai));
        float fg = 1.f / (1.f + expf(-af));
        float gg = tanhf(ag);
        float og = 1.f / (1.f + expf(-ao));
        float cn = fg * cs[b][jj] + ig * gg;
        cs[b][jj] = cn;
        float u = rintf(s.ut[b]);
        float hn = u * (og * tanhf(cn)) + (1.f - u) * hold[(size_t)b * HH + j];
        __stcg(hnew + (size_t)b * HH + j, hn);
        if (L1F) {
            out[((size_t)b * SS + t) * HH + j] = hn;
            sp += cn * sw[j];
        }
    }
    if (L1F) s.sred[tid] = sp;
}

__global__ void __launch_bounds__(256, 1) lstm_kernel(
    const float* __restrict__ x,
    const float* __restrict__ U0, const float* __restrict__ V0, const float* __restrict__ b0,
    const float* __restrict__ U1, const float* __restrict__ V1, const float* __restrict__ b1,
    const float* __restrict__ sw, const float* __restrict__ sb,
    float* __restrict__ out)
{
    __shared__ Smem s;
    const int tid = threadIdx.x, cb = blockIdx.x, j0 = cb * 8;
#pragma unroll
    for (int it = 0; it < 4; it++) {
        int e = it * 256 + tid;
        s.c0s[e & 127][e >> 7] = 0.f;
        s.c1s[e & 127][e >> 7] = 0.f;
    }
    if (tid < BB) s.ut[tid] = 1.f;
    __syncthreads();
    unsigned bt = 0;
    for (int t = 0; t < SS; t++) {
        int p = t & 1;
        cell<0>(s, tid, j0, t, x + (size_t)t * HH, (size_t)SS * HH, g_h0[p],
                U0, V0, b0, s.c0s, g_h0[p], g_h0[1 - p], sw, out);
        gbar(++bt);
        cell<1>(s, tid, j0, t, g_h0[1 - p], HH, g_h1[p],
                U1, V1, b1, s.c1s, g_h1[p], g_h1[1 - p], sw, out);
        __syncthreads();
        if (tid < BB) __stcg(&g_sp[cb][tid], s.sred[tid] + s.sred[tid + 128]);
        gbar(++bt);
        if (tid < BB) {
            float tot = sb[0];
            for (int q = 0; q < NB; q++) tot += __ldcg(&g_sp[q][tid]);
            float cum = 1.f / (1.f + expf(-tot));
            float utb = s.ut[tid];
            float u = rintf(utb);
            s.ut[tid] = (u > 0.5f) ? cum : (utb + fminf(cum, 1.f - utb));
        }
        __syncthreads();
    }
}

extern "C" void kernel_launch(void* const* d_in, const int* in_sizes, int n_in,
                              void* d_out, int out_size)
{
    const float* x  = (const float*)d_in[0];
    const float* U0 = (const float*)d_in[1];
    const float* V0 = (const float*)d_in[2];
    const float* b0 = (const float*)d_in[3];
    const float* U1 = (const float*)d_in[4];
    const float* V1 = (const float*)d_in[5];
    const float* b1 = (const float*)d_in[6];
    const float* sw = (const float*)d_in[7];
    const float* sb = (const float*)d_in[8];
    float* out = (float*)d_out;

    init_kernel<<<512, 256>>>();
    lstm_kernel<<<NB, 256>>>(x, U0, V0, b0, U1, V1, b1, sw, sb, out);
}

// round 4
// speedup vs baseline: 1.1022x; 1.1022x over previous
#include <cuda_runtime.h>
typedef unsigned long long ull;
#define BB 128
#define SS 512
#define HH 1024
#define NG 4096
#define KT 32
#define NCH 64
#define NB 128

__device__ float g_h0[2][BB * HH];
__device__ float g_h1[2][BB * HH];
__device__ float g_sp[NB][BB];
__device__ unsigned g_cnt, g_gen;

__device__ __forceinline__ void fma2(ull& a, ull x, ull y) {
    asm("fma.rn.f32x2 %0, %1, %2, %0;" : "+l"(a) : "l"(x), "l"(y));
}
__device__ __forceinline__ ull dup2(float w) {
    ull r; asm("mov.b64 %0, {%1, %1};" : "=l"(r) : "f"(w)); return r;
}

struct Smem {
    union { float Xs[KT][128]; float As[32][128]; };
    float Ws[KT][32];
    float c0s[BB][8];
    float c1s[BB][8];
    float ut[BB];
    float sred[256];
};

__global__ void init_kernel() {
    int i = blockIdx.x * blockDim.x + threadIdx.x;
    if (i < BB * HH) { g_h0[0][i] = 0.f; g_h1[0][i] = 0.f; }
    if (i == 0) { g_cnt = 0; g_gen = 0; }
}

__device__ __forceinline__ void gbar(unsigned target) {
    __syncthreads();
    if (threadIdx.x == 0) {
        __threadfence();
        if (atomicAdd(&g_cnt, 1u) == NB - 1) {
            g_cnt = 0;
            __threadfence();
            atomicAdd(&g_gen, 1u);
        } else {
            while (*(volatile unsigned*)&g_gen < target) {}
        }
        __threadfence();
    }
    __syncthreads();
}

// Load chunk ch's X/W fragment into registers (issued early; consumed at next STS).
__device__ __forceinline__ void load_chunk(
    int ch, int tid, int j0,
    const float* __restrict__ Xa, size_t lda, const float* __restrict__ Xb,
    const float* __restrict__ Wa, const float* __restrict__ Wb,
    float4 (&xr)[4], float (&wr)[4])
{
    const int k0 = ch * KT;
    const float* xs_; size_t str; const float* ws_; int kb;
    if (k0 < 1024) { xs_ = Xa; str = lda; ws_ = Wa; kb = k0; }
    else           { xs_ = Xb; str = HH;  ws_ = Wb; kb = k0 - 1024; }
    const int b = tid & 127;
#pragma unroll
    for (int it = 0; it < 4; it++) {
        int kq = it * 2 + (tid >> 7);
        xr[it] = __ldcg((const float4*)(xs_ + (size_t)b * str + kb + kq * 4));
    }
#pragma unroll
    for (int it = 0; it < 4; it++) {
        int idx = it * 256 + tid;
        int kk = idx >> 5, col = idx & 31;
        int n = (col >> 3) * HH + j0 + (col & 7);
        wr[it] = __ldg(ws_ + (size_t)(kb + kk) * NG + n);
    }
}

template <int L1F>
__device__ __forceinline__ void cell(
    Smem& s, int tid, int j0, int t,
    const float* __restrict__ Xa, size_t lda, const float* __restrict__ Xb,
    const float* __restrict__ Wa, const float* __restrict__ Wb,
    const float* __restrict__ bias, float (*cs)[8],
    const float* __restrict__ hold, float* __restrict__ hnew,
    const float* __restrict__ sw, float* __restrict__ out)
{
    const int rg = tid & 15, cg = tid >> 4;
    const int bsts = tid & 127;
    ull acc[4][2] = {};
    float4 xr[4];
    float wr[4];

    load_chunk(0, tid, j0, Xa, lda, Xb, Wa, Wb, xr, wr);

    for (int ch = 0; ch < NCH; ch++) {
        __syncthreads();    // prior consumers of Xs/Ws (or As) are done
        // ---- STS staged registers ----
#pragma unroll
        for (int it = 0; it < 4; it++) {
            int kk = (it * 2 + (tid >> 7)) * 4;
            s.Xs[kk + 0][bsts] = xr[it].x;
            s.Xs[kk + 1][bsts] = xr[it].y;
            s.Xs[kk + 2][bsts] = xr[it].z;
            s.Xs[kk + 3][bsts] = xr[it].w;
        }
#pragma unroll
        for (int it = 0; it < 4; it++) {
            int idx = it * 256 + tid;
            s.Ws[idx >> 5][idx & 31] = wr[it];
        }
        // ---- issue next chunk's global loads (latency hidden under compute) ----
        if (ch + 1 < NCH)
            load_chunk(ch + 1, tid, j0, Xa, lda, Xb, Wa, Wb, xr, wr);
        __syncthreads();    // staging visible
        // ---- compute ----
#pragma unroll
        for (int kk = 0; kk < KT; kk++) {
            ulonglong2 A0 = *(const ulonglong2*)&s.Xs[kk][4 * rg];
            ulonglong2 A1 = *(const ulonglong2*)&s.Xs[kk][64 + 4 * rg];
            float2 wv = *(const float2*)&s.Ws[kk][2 * cg];
            ull s0 = dup2(wv.x), s1 = dup2(wv.y);
            fma2(acc[0][0], A0.x, s0); fma2(acc[1][0], A0.y, s0);
            fma2(acc[2][0], A1.x, s0); fma2(acc[3][0], A1.y, s0);
            fma2(acc[0][1], A0.x, s1); fma2(acc[1][1], A0.y, s1);
            fma2(acc[2][1], A1.x, s1); fma2(acc[3][1], A1.y, s1);
        }
    }
    __syncthreads();        // all warps done reading Xs before As overwrite
#pragma unroll
    for (int c = 0; c < 2; c++) {
        *(ull*)&s.As[2 * cg + c][4 * rg]          = acc[0][c];
        *(ull*)&s.As[2 * cg + c][4 * rg + 2]      = acc[1][c];
        *(ull*)&s.As[2 * cg + c][64 + 4 * rg]     = acc[2][c];
        *(ull*)&s.As[2 * cg + c][64 + 4 * rg + 2] = acc[3][c];
    }
    __syncthreads();
    float sp = 0.f;
#pragma unroll
    for (int it = 0; it < 4; it++) {
        int e = it * 256 + tid;
        int b = e & 127, jj = e >> 7;
        int j = j0 + jj;
        float ai = s.As[jj][b]      + bias[j];
        float af = s.As[8 + jj][b]  + bias[HH + j];
        float ag = s.As[16 + jj][b] + bias[2 * HH + j];
        float ao = s.As[24 + jj][b] + bias[3 * HH + j];
        float ig = 1.f / (1.f + expf(-ai));
        float fg = 1.f / (1.f + expf(-af));
        float gg = tanhf(ag);
        float og = 1.f / (1.f + expf(-ao));
        float cn = fg * cs[b][jj] + ig * gg;
        cs[b][jj] = cn;
        float u = rintf(s.ut[b]);
        float hn = u * (og * tanhf(cn)) + (1.f - u) * hold[(size_t)b * HH + j];
        __stcg(hnew + (size_t)b * HH + j, hn);
        if (L1F) {
            out[((size_t)b * SS + t) * HH + j] = hn;
            sp += cn * sw[j];
        }
    }
    if (L1F) s.sred[tid] = sp;
}

__global__ void __launch_bounds__(256, 1) lstm_kernel(
    const float* __restrict__ x,
    const float* __restrict__ U0, const float* __restrict__ V0, const float* __restrict__ b0,
    const float* __restrict__ U1, const float* __restrict__ V1, const float* __restrict__ b1,
    const float* __restrict__ sw, const float* __restrict__ sb,
    float* __restrict__ out)
{
    __shared__ Smem s;
    const int tid = threadIdx.x, cb = blockIdx.x, j0 = cb * 8;
#pragma unroll
    for (int it = 0; it < 4; it++) {
        int e = it * 256 + tid;
        s.c0s[e & 127][e >> 7] = 0.f;
        s.c1s[e & 127][e >> 7] = 0.f;
    }
    if (tid < BB) s.ut[tid] = 1.f;
    __syncthreads();
    unsigned bt = 0;
    for (int t = 0; t < SS; t++) {
        int p = t & 1;
        cell<0>(s, tid, j0, t, x + (size_t)t * HH, (size_t)SS * HH, g_h0[p],
                U0, V0, b0, s.c0s, g_h0[p], g_h0[1 - p], sw, out);
        gbar(++bt);
        cell<1>(s, tid, j0, t, g_h0[1 - p], HH, g_h1[p],
                U1, V1, b1, s.c1s, g_h1[p], g_h1[1 - p], sw, out);
        __syncthreads();
        if (tid < BB) __stcg(&g_sp[cb][tid], s.sred[tid] + s.sred[tid + 128]);
        gbar(++bt);
        if (tid < BB) {
            float tot = sb[0];
#pragma unroll 8
            for (int q = 0; q < NB; q++) tot += __ldcg(&g_sp[q][tid]);
            float cum = 1.f / (1.f + expf(-tot));
            float utb = s.ut[tid];
            float u = rintf(utb);
            s.ut[tid] = (u > 0.5f) ? cum : (utb + fminf(cum, 1.f - utb));
        }
        __syncthreads();
    }
}

extern "C" void kernel_launch(void* const* d_in, const int* in_sizes, int n_in,
                              void* d_out, int out_size)
{
    const float* x  = (const float*)d_in[0];
    const float* U0 = (const float*)d_in[1];
    const float* V0 = (const float*)d_in[2];
    const float* b0 = (const float*)d_in[3];
    const float* U1 = (const float*)d_in[4];
    const float* V1 = (const float*)d_in[5];
    const float* b1 = (const float*)d_in[6];
    const float* sw = (const float*)d_in[7];
    const float* sb = (const float*)d_in[8];
    float* out = (float*)d_out;

    init_kernel<<<512, 256>>>();
    lstm_kernel<<<NB, 256>>>(x, U0, V0, b0, U1, V1, b1, sw, sb, out);
}

// round 6
// speedup vs baseline: 3.7494x; 3.4018x over previous
#include <cuda_runtime.h>
#include <cuda_bf16.h>
#include <cstdint>

typedef uint32_t u32; typedef uint64_t u64;

#define NB 128
#define SS 512
#define HH 1024
#define NCHK 32

// ---------- persistent device state ----------
__device__ __nv_bfloat16 g_W0h[8388608], g_W0l[8388608];   // [n'=j*4+g][k] (k contig, 2048)
__device__ __nv_bfloat16 g_W1h[8388608], g_W1l[8388608];
__device__ __nv_bfloat16 g_h0h[2][131072], g_h0l[2][131072];
__device__ __nv_bfloat16 g_h1h[2][131072], g_h1l[2][131072];
__device__ float g_sp[128][128];   // [b][cb]
__device__ unsigned g_cnt, g_gen;

// ---------- helpers ----------
__device__ __forceinline__ u32 smem_u32(const void* p) {
    u32 a; asm("{ .reg .u64 t; cvta.to.shared.u64 t, %1; cvt.u32.u64 %0, t; }" : "=r"(a) : "l"(p));
    return a;
}
__device__ __forceinline__ void ldsm4(u32 a, u32& r0, u32& r1, u32& r2, u32& r3) {
    asm volatile("ldmatrix.sync.aligned.m8n8.x4.shared.b16 {%0,%1,%2,%3}, [%4];"
        : "=r"(r0), "=r"(r1), "=r"(r2), "=r"(r3) : "r"(a));
}
__device__ __forceinline__ void mma16816(float* c, u32 a0, u32 a1, u32 a2, u32 a3, u32 b0, u32 b1) {
    asm volatile("mma.sync.aligned.m16n8k16.row.col.f32.bf16.bf16.f32 "
        "{%0,%1,%2,%3}, {%4,%5,%6,%7}, {%8,%9}, {%0,%1,%2,%3};"
        : "+f"(c[0]), "+f"(c[1]), "+f"(c[2]), "+f"(c[3])
        : "r"(a0), "r"(a1), "r"(a2), "r"(a3), "r"(b0), "r"(b1));
}
__device__ __forceinline__ u32 pkbf2(float f0, float f1) {  // mem order [f0,f1]
    u32 r; asm("cvt.rn.bf16x2.f32 %0, %1, %2;" : "=r"(r) : "f"(f1), "f"(f0)); return r;
}
__device__ __forceinline__ void cvt8(uint4& hi, uint4& lo, float4 a, float4 b) {
    hi.x = pkbf2(a.x, a.y); hi.y = pkbf2(a.z, a.w);
    hi.z = pkbf2(b.x, b.y); hi.w = pkbf2(b.z, b.w);
    lo.x = pkbf2(a.x - __uint_as_float(hi.x << 16), a.y - __uint_as_float(hi.x & 0xffff0000u));
    lo.y = pkbf2(a.z - __uint_as_float(hi.y << 16), a.w - __uint_as_float(hi.y & 0xffff0000u));
    lo.z = pkbf2(b.x - __uint_as_float(hi.z << 16), b.y - __uint_as_float(hi.z & 0xffff0000u));
    lo.w = pkbf2(b.z - __uint_as_float(hi.w << 16), b.w - __uint_as_float(hi.w & 0xffff0000u));
}
__device__ __forceinline__ void sts16(char* base, int off, uint4 v) {
    *(uint4*)(base + (off ^ ((off >> 3) & 0x70))) = v;
}

// ---------- init kernels ----------
__global__ void init_kernel() {
    int i = blockIdx.x * blockDim.x + threadIdx.x;
    __nv_bfloat16 z = __float2bfloat16(0.f);
    if (i < 131072) { g_h0h[0][i] = z; g_h0l[0][i] = z; g_h1h[0][i] = z; g_h1l[0][i] = z; }
    if (i == 0) { g_cnt = 0; g_gen = 0; }
}
__global__ void conv_w(const float* __restrict__ U0, const float* __restrict__ V0,
                       const float* __restrict__ U1, const float* __restrict__ V1) {
    size_t i = (size_t)blockIdx.x * 256 + threadIdx.x;   // 2 * 4096 * 2048
    int layer = (int)(i >> 23);
    size_t r = i & 8388607;
    int np = (int)(r >> 11), k = (int)(r & 2047);
    int g = np & 3, j = np >> 2;
    const float* src = layer ? (k < 1024 ? U1 : V1) : (k < 1024 ? U0 : V0);
    float v = src[(size_t)(k & 1023) * 4096 + g * 1024 + j];
    __nv_bfloat16 hi = __float2bfloat16(v);
    __nv_bfloat16 lo = __float2bfloat16(v - __bfloat162float(hi));
    if (layer) { g_W1h[r] = hi; g_W1l[r] = lo; }
    else       { g_W0h[r] = hi; g_W0l[r] = lo; }
}

// ---------- grid barrier ----------
__device__ __forceinline__ void gbar(unsigned target) {
    __syncthreads();
    if (threadIdx.x == 0) {
        __threadfence();
        if (atomicAdd(&g_cnt, 1u) == NB - 1) {
            g_cnt = 0; __threadfence(); atomicAdd(&g_gen, 1u);
        } else {
            while (*(volatile unsigned*)&g_gen < target) {}
        }
        __threadfence();
    }
    __syncthreads();
}

// ---------- staged fragment load ----------
struct Frag { uint4 ah[4], al[4], bh, bl; };

template <int CELL>
__device__ __forceinline__ void load_frag(Frag& f, int ch, int t, int p, int n0, int tid,
                                          const float* __restrict__ x) {
    const int k0 = ch * 64;
    {
        const __nv_bfloat16* Wh = CELL ? g_W1h : g_W0h;
        const __nv_bfloat16* Wl = CELL ? g_W1l : g_W0l;
        size_t wo = (size_t)(n0 + (tid >> 3)) * 2048 + k0 + (tid & 7) * 8;
        f.bh = __ldg((const uint4*)(Wh + wo));
        f.bl = __ldg((const uint4*)(Wl + wo));
    }
    if (CELL == 0 && ch < 16) {
#pragma unroll
        for (int it = 0; it < 4; it++) {
            int slot = it * 256 + tid;
            int b = slot >> 3, k = k0 + (slot & 7) * 8;
            const float* src = x + ((size_t)b * SS + t) * HH + k;
            float4 v0 = __ldg((const float4*)src);
            float4 v1 = __ldg((const float4*)(src + 4));
            cvt8(f.ah[it], f.al[it], v0, v1);
        }
    } else {
        const __nv_bfloat16 *sh, *sl;
        if (CELL == 0)      { sh = g_h0h[p];     sl = g_h0l[p]; }
        else if (ch < 16)   { sh = g_h0h[1 - p]; sl = g_h0l[1 - p]; }
        else                { sh = g_h1h[p];     sl = g_h1l[p]; }
        int kb = k0 & 1023;
#pragma unroll
        for (int it = 0; it < 4; it++) {
            int slot = it * 256 + tid;
            int b = slot >> 3, k = kb + (slot & 7) * 8;
            size_t o = (size_t)b * HH + k;
            f.ah[it] = __ldcg((const uint4*)(sh + o));
            f.al[it] = __ldcg((const uint4*)(sl + o));
        }
    }
}

struct SmemT {
    union {
        struct { char Ah[16384]; char Al[16384]; char Bh[4096]; char Bl[4096]; } st;
        float As[32][129];
    } uu;
    float bias[2][32];
    float sw8[8];
};

// ---------- GEMM: acc[4][4] covers rows 16w..16w+15 x cols 0..31 ----------
template <int CELL>
__device__ __forceinline__ void run_gemm(SmemT& s, const float* __restrict__ x,
    int t, int p, int n0, int tid, float acc[4][4],
    u32 bAh, u32 bAl, u32 bBh, u32 bBl)
{
    const int lane = tid & 31, w = tid >> 5;
    const int arow = 16 * w + (lane & 15);
    const int akhi = lane >> 4;                 // +0/+1 k16
    const int brow = (lane & 7) + ((lane >> 4) << 3);
    const int bkhi = (lane >> 3) & 1;
    const u32 aoff = (u32)arow * 128;
    const int asw = arow & 7;
    const u32 boff = (u32)brow * 128;
    const int bsw = brow & 7;

    Frag f;
    load_frag<CELL>(f, 0, t, p, n0, tid, x);
#pragma unroll 1
    for (int ch = 0; ch < NCHK; ch++) {
        __syncthreads();    // previous chunk's ldmatrix reads complete
        {
            int off = (tid >> 3) * 128 + (tid & 7) * 16;
            sts16(s.uu.st.Bh, off, f.bh);
            sts16(s.uu.st.Bl, off, f.bl);
#pragma unroll
            for (int it = 0; it < 4; it++) {
                int slot = it * 256 + tid;
                int o2 = (slot >> 3) * 128 + (slot & 7) * 16;
                sts16(s.uu.st.Ah, o2, f.ah[it]);
                sts16(s.uu.st.Al, o2, f.al[it]);
            }
        }
        if (ch + 1 < NCHK) load_frag<CELL>(f, ch + 1, t, p, n0, tid, x);
        __syncthreads();    // staging visible
#pragma unroll
        for (int sp = 0; sp < 3; sp++) {
            u32 Ab = ((sp == 2) ? bAl : bAh) + aoff;
            u32 Bb = ((sp == 1) ? bBl : bBh) + boff;
#pragma unroll
            for (int ks = 0; ks < 4; ks++) {
                int ak = 2 * ks + akhi;
                u32 a0, a1, a2, a3;
                ldsm4(Ab + ((ak ^ asw) << 4), a0, a1, a2, a3);
                int bk = 2 * ks + bkhi;
                u32 blo = Bb + ((bk ^ bsw) << 4);
                u32 b0, b1, b2, b3, b4, b5, b6, b7;
                ldsm4(blo, b0, b1, b2, b3);
                ldsm4(blo + 16 * 128, b4, b5, b6, b7);
                mma16816(acc[0], a0, a1, a2, a3, b0, b1);
                mma16816(acc[1], a0, a1, a2, a3, b2, b3);
                mma16816(acc[2], a0, a1, a2, a3, b4, b5);
                mma16816(acc[3], a0, a1, a2, a3, b6, b7);
            }
        }
    }
    __syncthreads();        // all ldmatrix done before As overwrite
#pragma unroll
    for (int fr = 0; fr < 4; fr++) {
        int nn = fr * 8 + 2 * (lane & 3);
        int r = 16 * w + (lane >> 2);
        s.uu.As[nn][r]         = acc[fr][0];
        s.uu.As[nn + 1][r]     = acc[fr][1];
        s.uu.As[nn][r + 8]     = acc[fr][2];
        s.uu.As[nn + 1][r + 8] = acc[fr][3];
    }
    __syncthreads();
}

// ---------- main persistent kernel ----------
__global__ void __launch_bounds__(256, 1) lstm_kernel(
    const float* __restrict__ x,
    const float* __restrict__ b0, const float* __restrict__ b1,
    const float* __restrict__ sw, const float* __restrict__ sb,
    float* __restrict__ out) {
    __shared__ alignas(1024) SmemT s;

    const int tid = threadIdx.x, cb = blockIdx.x;
    const int j0 = cb * 8, n0 = cb * 32;

    if (tid < 64) {
        int layer = tid >> 5, c = tid & 31;
        const float* bp = layer ? b1 : b0;
        s.bias[layer][c] = bp[(c & 3) * 1024 + j0 + (c >> 2)];
    }
    if (tid < 8) s.sw8[tid] = sw[j0 + tid];
    __syncthreads();

    const u32 bAh = smem_u32(s.uu.st.Ah), bAl = smem_u32(s.uu.st.Al);
    const u32 bBh = smem_u32(s.uu.st.Bh), bBl = smem_u32(s.uu.st.Bl);

    float c0r[8] = {}, c1r[8] = {}, h0r[8] = {}, h1r[8] = {};
    float ut = 1.f;
    unsigned bt = 0;

#pragma unroll 1
    for (int t = 0; t < SS; t++) {
        const int p = t & 1;
        // ===== layer 0 =====
        {
            float acc[4][4] = {};
            run_gemm<0>(s, x, t, p, n0, tid, acc, bAh, bAl, bBh, bBl);
        }
        if (tid < 128) {
            int b = tid;
            float u = rintf(ut);
#pragma unroll
            for (int jj = 0; jj < 8; jj++) {
                float ai = s.uu.As[jj * 4 + 0][b] + s.bias[0][jj * 4 + 0];
                float af = s.uu.As[jj * 4 + 1][b] + s.bias[0][jj * 4 + 1];
                float ag = s.uu.As[jj * 4 + 2][b] + s.bias[0][jj * 4 + 2];
                float ao = s.uu.As[jj * 4 + 3][b] + s.bias[0][jj * 4 + 3];
                float ig = 1.f / (1.f + expf(-ai));
                float fg = 1.f / (1.f + expf(-af));
                float gg = tanhf(ag);
                float og = 1.f / (1.f + expf(-ao));
                float cn = fg * c0r[jj] + ig * gg;
                c0r[jj] = cn;
                float hn = u * (og * tanhf(cn)) + (1.f - u) * h0r[jj];
                h0r[jj] = hn;
                __nv_bfloat16 hi = __float2bfloat16(hn);
                __stcg(&g_h0h[1 - p][(size_t)b * HH + j0 + jj], hi);
                __stcg(&g_h0l[1 - p][(size_t)b * HH + j0 + jj],
                       __float2bfloat16(hn - __bfloat162float(hi)));
            }
        }
        gbar(++bt);
        // ===== layer 1 =====
        {
            float acc[4][4] = {};
            run_gemm<1>(s, x, t, p, n0, tid, acc, bAh, bAl, bBh, bBl);
        }
        if (tid < 128) {
            int b = tid;
            float u = rintf(ut);
            float sp = 0.f;
#pragma unroll
            for (int jj = 0; jj < 8; jj++) {
                float ai = s.uu.As[jj * 4 + 0][b] + s.bias[1][jj * 4 + 0];
                float af = s.uu.As[jj * 4 + 1][b] + s.bias[1][jj * 4 + 1];
                float ag = s.uu.As[jj * 4 + 2][b] + s.bias[1][jj * 4 + 2];
                float ao = s.uu.As[jj * 4 + 3][b] + s.bias[1][jj * 4 + 3];
                float ig = 1.f / (1.f + expf(-ai));
                float fg = 1.f / (1.f + expf(-af));
                float gg = tanhf(ag);
                float og = 1.f / (1.f + expf(-ao));
                float cn = fg * c1r[jj] + ig * gg;
                c1r[jj] = cn;
                sp += cn * s.sw8[jj];
                float hn = u * (og * tanhf(cn)) + (1.f - u) * h1r[jj];
                h1r[jj] = hn;
                __nv_bfloat16 hi = __float2bfloat16(hn);
                __stcg(&g_h1h[1 - p][(size_t)b * HH + j0 + jj], hi);
                __stcg(&g_h1l[1 - p][(size_t)b * HH + j0 + jj],
                       __float2bfloat16(hn - __bfloat162float(hi)));
                out[((size_t)b * SS + t) * HH + j0 + jj] = hn;
            }
            __stcg(&g_sp[b][cb], sp);
        }
        gbar(++bt);
        if (tid < 128) {
            float tot = sb[0];
            const float4* q = (const float4*)&g_sp[tid][0];
#pragma unroll
            for (int i = 0; i < 32; i++) {
                float4 v = __ldcg(q + i);
                tot += v.x + v.y + v.z + v.w;
            }
            float cum = 1.f / (1.f + expf(-tot));
            float u = rintf(ut);
            ut = (u > 0.5f) ? cum : (ut + fminf(cum, 1.f - ut));
        }
        __syncthreads();
    }
}

extern "C" void kernel_launch(void* const* d_in, const int* in_sizes, int n_in,
                              void* d_out, int out_size) {
    (void)in_sizes; (void)n_in; (void)out_size;
    const float* x  = (const float*)d_in[0];
    const float* U0 = (const float*)d_in[1];
    const float* V0 = (const float*)d_in[2];
    const float* b0 = (const float*)d_in[3];
    const float* U1 = (const float*)d_in[4];
    const float* V1 = (const float*)d_in[5];
    const float* b1 = (const float*)d_in[6];
    const float* sw = (const float*)d_in[7];
    const float* sb = (const float*)d_in[8];
    float* out = (float*)d_out;

    init_kernel<<<512, 256>>>();
    conv_w<<<65536, 256>>>(U0, V0, U1, V1);
    lstm_kernel<<<NB, 256>>>(x, b0, b1, sw, sb, out);
}

// round 8
// speedup vs baseline: 4.1102x; 1.0962x over previous
#include <cuda_runtime.h>
#include <cuda_bf16.h>
#include <cstdint>

typedef uint32_t u32; typedef uint64_t u64;

#define NB 128
#define SS 512
#define HH 1024
#define NCHK 32
#define STG_A 16384
#define STG_B 4096
#define STG_STRIDE (2 * STG_A + 2 * STG_B)   // 40960
#define SMEM_DYN (2 * STG_STRIDE)            // 81920

// ---------- persistent device state ----------
__device__ __nv_bfloat16 g_W0h[8388608], g_W0l[8388608];   // [n'=j*4+g][k] (k contig, 2048)
__device__ __nv_bfloat16 g_W1h[8388608], g_W1l[8388608];
__device__ __nv_bfloat16 g_h0h[2][131072], g_h0l[2][131072];
__device__ __nv_bfloat16 g_h1h[2][131072], g_h1l[2][131072];
__device__ float g_sp[128][128];   // [b][cb]
__device__ unsigned g_cnt, g_gen;

// ---------- helpers ----------
__device__ __forceinline__ u32 smem_u32(const void* p) {
    u32 a; asm("{ .reg .u64 t; cvta.to.shared.u64 t, %1; cvt.u32.u64 %0, t; }" : "=r"(a) : "l"(p));
    return a;
}
__device__ __forceinline__ void ldsm4(u32 a, u32& r0, u32& r1, u32& r2, u32& r3) {
    asm volatile("ldmatrix.sync.aligned.m8n8.x4.shared.b16 {%0,%1,%2,%3}, [%4];"
        : "=r"(r0), "=r"(r1), "=r"(r2), "=r"(r3) : "r"(a));
}
__device__ __forceinline__ void mma16816(float* c, const u32* a, u32 b0, u32 b1) {
    asm volatile("mma.sync.aligned.m16n8k16.row.col.f32.bf16.bf16.f32 "
        "{%0,%1,%2,%3}, {%4,%5,%6,%7}, {%8,%9}, {%0,%1,%2,%3};"
        : "+f"(c[0]), "+f"(c[1]), "+f"(c[2]), "+f"(c[3])
        : "r"(a[0]), "r"(a[1]), "r"(a[2]), "r"(a[3]), "r"(b0), "r"(b1));
}
__device__ __forceinline__ u32 pkbf2(float f0, float f1) {  // mem order [f0,f1]
    u32 r; asm("cvt.rn.bf16x2.f32 %0, %1, %2;" : "=r"(r) : "f"(f1), "f"(f0)); return r;
}
__device__ __forceinline__ void cvt8(uint4& hi, uint4& lo, float4 a, float4 b) {
    hi.x = pkbf2(a.x, a.y); hi.y = pkbf2(a.z, a.w);
    hi.z = pkbf2(b.x, b.y); hi.w = pkbf2(b.z, b.w);
    lo.x = pkbf2(a.x - __uint_as_float(hi.x << 16), a.y - __uint_as_float(hi.x & 0xffff0000u));
    lo.y = pkbf2(a.z - __uint_as_float(hi.y << 16), a.w - __uint_as_float(hi.y & 0xffff0000u));
    lo.z = pkbf2(b.x - __uint_as_float(hi.z << 16), b.y - __uint_as_float(hi.z & 0xffff0000u));
    lo.w = pkbf2(b.z - __uint_as_float(hi.w << 16), b.w - __uint_as_float(hi.w & 0xffff0000u));
}
__device__ __forceinline__ void sts16(char* base, int off, uint4 v) {
    *(uint4*)(base + (off ^ ((off >> 3) & 0x70))) = v;
}

// ---------- init kernels ----------
__global__ void init_kernel() {
    int i = blockIdx.x * blockDim.x + threadIdx.x;
    __nv_bfloat16 z = __float2bfloat16(0.f);
    if (i < 131072) { g_h0h[0][i] = z; g_h0l[0][i] = z; g_h1h[0][i] = z; g_h1l[0][i] = z; }
    if (i == 0) { g_cnt = 0; g_gen = 0; }
}
__global__ void conv_w(const float* __restrict__ U0, const float* __restrict__ V0,
                       const float* __restrict__ U1, const float* __restrict__ V1) {
    size_t i = (size_t)blockIdx.x * 256 + threadIdx.x;   // 2 * 4096 * 2048
    int layer = (int)(i >> 23);
    size_t r = i & 8388607;
    int np = (int)(r >> 11), k = (int)(r & 2047);
    int g = np & 3, j = np >> 2;
    const float* src = layer ? (k < 1024 ? U1 : V1) : (k < 1024 ? U0 : V0);
    float v = src[(size_t)(k & 1023) * 4096 + g * 1024 + j];
    __nv_bfloat16 hi = __float2bfloat16(v);
    __nv_bfloat16 lo = __float2bfloat16(v - __bfloat162float(hi));
    if (layer) { g_W1h[r] = hi; g_W1l[r] = lo; }
    else       { g_W0h[r] = hi; g_W0l[r] = lo; }
}

// ---------- grid barrier ----------
__device__ __forceinline__ void gbar(unsigned target) {
    __syncthreads();
    if (threadIdx.x == 0) {
        __threadfence();
        if (atomicAdd(&g_cnt, 1u) == NB - 1) {
            g_cnt = 0; __threadfence(); atomicAdd(&g_gen, 1u);
        } else {
            while (*(volatile unsigned*)&g_gen < target) {}
        }
        __threadfence();
    }
    __syncthreads();
}

// ---------- staged fragment load ----------
struct Frag { uint4 ah[4], al[4], bh, bl; };

template <int CELL>
__device__ __forceinline__ void load_frag(Frag& f, int ch, int t, int p, int n0, int tid,
                                          const float* __restrict__ x) {
    const int k0 = ch * 64;
    {
        const __nv_bfloat16* Wh = CELL ? g_W1h : g_W0h;
        const __nv_bfloat16* Wl = CELL ? g_W1l : g_W0l;
        size_t wo = (size_t)(n0 + (tid >> 3)) * 2048 + k0 + (tid & 7) * 8;
        f.bh = __ldg((const uint4*)(Wh + wo));
        f.bl = __ldg((const uint4*)(Wl + wo));
    }
    if (CELL == 0 && ch < 16) {
#pragma unroll
        for (int it = 0; it < 4; it++) {
            int slot = it * 256 + tid;
            int b = slot >> 3, k = k0 + (slot & 7) * 8;
            const float* src = x + ((size_t)b * SS + t) * HH + k;
            float4 v0 = __ldg((const float4*)src);
            float4 v1 = __ldg((const float4*)(src + 4));
            cvt8(f.ah[it], f.al[it], v0, v1);
        }
    } else {
        const __nv_bfloat16 *sh, *sl;
        if (CELL == 0)      { sh = g_h0h[p];     sl = g_h0l[p]; }
        else if (ch < 16)   { sh = g_h0h[1 - p]; sl = g_h0l[1 - p]; }
        else                { sh = g_h1h[p];     sl = g_h1l[p]; }
        int kb = k0 & 1023;
#pragma unroll
        for (int it = 0; it < 4; it++) {
            int slot = it * 256 + tid;
            int b = slot >> 3, k = kb + (slot & 7) * 8;
            size_t o = (size_t)b * HH + k;
            f.ah[it] = __ldcg((const uint4*)(sh + o));
            f.al[it] = __ldcg((const uint4*)(sl + o));
        }
    }
}

__device__ __forceinline__ void sts_frag(char* stage, const Frag& f, int tid) {
    int off = (tid >> 3) * 128 + (tid & 7) * 16;
    sts16(stage + 2 * STG_A, off, f.bh);
    sts16(stage + 2 * STG_A + STG_B, off, f.bl);
#pragma unroll
    for (int it = 0; it < 4; it++) {
        int slot = it * 256 + tid;
        int o2 = (slot >> 3) * 128 + (slot & 7) * 16;
        sts16(stage, o2, f.ah[it]);
        sts16(stage + STG_A, o2, f.al[it]);
    }
}

struct SmemT {
    float As[32][129];
    float bias[2][32];
    float sw8[8];
};

// ---------- GEMM: acc[4][4] covers rows 16w..16w+15 x cols 0..31 ----------
template <int CELL>
__device__ __forceinline__ void run_gemm(SmemT& s, char* dyn, const float* __restrict__ x,
    int t, int p, int n0, int tid, float acc[4][4], u32 dynb)
{
    const int lane = tid & 31, w = tid >> 5;
    const int arow = 16 * w + (lane & 15);
    const int akhi = lane >> 4;
    const int brow = (lane & 7) + ((lane >> 4) << 3);
    const int bkhi = (lane >> 3) & 1;
    const u32 aoff = (u32)arow * 128;
    const int asw = arow & 7;
    const u32 boff = (u32)brow * 128;
    const int bsw = brow & 7;

    Frag f;
    load_frag<CELL>(f, 0, t, p, n0, tid, x);
    sts_frag(dyn, f, tid);
    load_frag<CELL>(f, 1, t, p, n0, tid, x);
    __syncthreads();

#pragma unroll 1
    for (int ch = 0; ch < NCHK; ch++) {
        if (ch + 1 < NCHK) sts_frag(dyn + ((ch + 1) & 1) * STG_STRIDE, f, tid);
        if (ch + 2 < NCHK) load_frag<CELL>(f, ch + 2, t, p, n0, tid, x);
        const u32 base = dynb + (u32)((ch & 1) * STG_STRIDE);
        const u32 aAh = base + aoff;
        const u32 aAl = base + STG_A + aoff;
        const u32 aBh = base + 2 * STG_A + boff;
        const u32 aBl = base + 2 * STG_A + STG_B + boff;
#pragma unroll
        for (int ks = 0; ks < 4; ks++) {
            const u32 ao = (u32)(((2 * ks + akhi) ^ asw) << 4);
            const u32 bo = (u32)(((2 * ks + bkhi) ^ bsw) << 4);
            u32 ah[4], al[4], bh[8], bl[8];
            ldsm4(aAh + ao, ah[0], ah[1], ah[2], ah[3]);
            ldsm4(aAl + ao, al[0], al[1], al[2], al[3]);
            ldsm4(aBh + bo, bh[0], bh[1], bh[2], bh[3]);
            ldsm4(aBh + 16 * 128 + bo, bh[4], bh[5], bh[6], bh[7]);
            ldsm4(aBl + bo, bl[0], bl[1], bl[2], bl[3]);
            ldsm4(aBl + 16 * 128 + bo, bl[4], bl[5], bl[6], bl[7]);
            mma16816(acc[0], ah, bh[0], bh[1]);
            mma16816(acc[1], ah, bh[2], bh[3]);
            mma16816(acc[2], ah, bh[4], bh[5]);
            mma16816(acc[3], ah, bh[6], bh[7]);
            mma16816(acc[0], ah, bl[0], bl[1]);
            mma16816(acc[1], ah, bl[2], bl[3]);
            mma16816(acc[2], ah, bl[4], bl[5]);
            mma16816(acc[3], ah, bl[6], bl[7]);
            mma16816(acc[0], al, bh[0], bh[1]);
            mma16816(acc[1], al, bh[2], bh[3]);
            mma16816(acc[2], al, bh[4], bh[5]);
            mma16816(acc[3], al, bh[6], bh[7]);
        }
        __syncthreads();
    }
    // park acc in As (separate static buffer -> no hazard with stages)
#pragma unroll
    for (int fr = 0; fr < 4; fr++) {
        int nn = fr * 8 + 2 * (lane & 3);
        int r = 16 * w + (lane >> 2);
        s.As[nn][r]         = acc[fr][0];
        s.As[nn + 1][r]     = acc[fr][1];
        s.As[nn][r + 8]     = acc[fr][2];
        s.As[nn + 1][r + 8] = acc[fr][3];
    }
    __syncthreads();
}

// ---------- main persistent kernel ----------
__global__ void __launch_bounds__(256, 1) lstm_kernel(
    const float* __restrict__ x,
    const float* __restrict__ b0, const float* __restrict__ b1,
    const float* __restrict__ sw, const float* __restrict__ sb,
    float* __restrict__ out) {
    extern __shared__ __align__(1024) char dyn[];
    __shared__ SmemT s;

    const int tid = threadIdx.x, cb = blockIdx.x;
    const int j0 = cb * 8, n0 = cb * 32;

    if (tid < 64) {
        int layer = tid >> 5, c = tid & 31;
        const float* bp = layer ? b1 : b0;
        s.bias[layer][c] = bp[(c & 3) * 1024 + j0 + (c >> 2)];
    }
    if (tid < 8) s.sw8[tid] = sw[j0 + tid];
    __syncthreads();

    const u32 dynb = smem_u32(dyn);

    float c0r[8] = {}, c1r[8] = {}, h0r[8] = {}, h1r[8] = {};
    float ut = 1.f;
    unsigned bt = 0;

#pragma unroll 1
    for (int t = 0; t < SS; t++) {
        const int p = t & 1;
        // ===== layer 0 =====
        {
            float acc[4][4] = {};
            run_gemm<0>(s, dyn, x, t, p, n0, tid, acc, dynb);
        }
        if (tid < 128) {
            int b = tid;
            float u = rintf(ut);
#pragma unroll
            for (int jj = 0; jj < 8; jj++) {
                float ai = s.As[jj * 4 + 0][b] + s.bias[0][jj * 4 + 0];
                float af = s.As[jj * 4 + 1][b] + s.bias[0][jj * 4 + 1];
                float ag = s.As[jj * 4 + 2][b] + s.bias[0][jj * 4 + 2];
                float ao = s.As[jj * 4 + 3][b] + s.bias[0][jj * 4 + 3];
                float ig = 1.f / (1.f + expf(-ai));
                float fg = 1.f / (1.f + expf(-af));
                float gg = tanhf(ag);
                float og = 1.f / (1.f + expf(-ao));
                float cn = fg * c0r[jj] + ig * gg;
                c0r[jj] = cn;
                float hn = u * (og * tanhf(cn)) + (1.f - u) * h0r[jj];
                h0r[jj] = hn;
                __nv_bfloat16 hi = __float2bfloat16(hn);
                __stcg(&g_h0h[1 - p][(size_t)b * HH + j0 + jj], hi);
                __stcg(&g_h0l[1 - p][(size_t)b * HH + j0 + jj],
                       __float2bfloat16(hn - __bfloat162float(hi)));
            }
        }
        gbar(++bt);
        // ===== layer 1 =====
        {
            float acc[4][4] = {};
            run_gemm<1>(s, dyn, x, t, p, n0, tid, acc, dynb);
        }
        if (tid < 128) {
            int b = tid;
            float u = rintf(ut);
            float sp = 0.f;
#pragma unroll
            for (int jj = 0; jj < 8; jj++) {
                float ai = s.As[jj * 4 + 0][b] + s.bias[1][jj * 4 + 0];
                float af = s.As[jj * 4 + 1][b] + s.bias[1][jj * 4 + 1];
                float ag = s.As[jj * 4 + 2][b] + s.bias[1][jj * 4 + 2];
                float ao = s.As[jj * 4 + 3][b] + s.bias[1][jj * 4 + 3];
                float ig = 1.f / (1.f + expf(-ai));
                float fg = 1.f / (1.f + expf(-af));
                float gg = tanhf(ag);
                float og = 1.f / (1.f + expf(-ao));
                float cn = fg * c1r[jj] + ig * gg;
                c1r[jj] = cn;
                sp += cn * s.sw8[jj];
                float hn = u * (og * tanhf(cn)) + (1.f - u) * h1r[jj];
                h1r[jj] = hn;
                __nv_bfloat16 hi = __float2bfloat16(hn);
                __stcg(&g_h1h[1 - p][(size_t)b * HH + j0 + jj], hi);
                __stcg(&g_h1l[1 - p][(size_t)b * HH + j0 + jj],
                       __float2bfloat16(hn - __bfloat162float(hi)));
                out[((size_t)b * SS + t) * HH + j0 + jj] = hn;
            }
            __stcg(&g_sp[b][cb], sp);
        }
        gbar(++bt);
        if (tid < 128) {
            float tot = sb[0];
            const float4* q = (const float4*)&g_sp[tid][0];
#pragma unroll
            for (int i = 0; i < 32; i++) {
                float4 v = __ldcg(q + i);
                tot += v.x + v.y + v.z + v.w;
            }
            float cum = 1.f / (1.f + expf(-tot));
            float u = rintf(ut);
            ut = (u > 0.5f) ? cum : (ut + fminf(cum, 1.f - ut));
        }
        __syncthreads();
    }
}

extern "C" void kernel_launch(void* const* d_in, const int* in_sizes, int n_in,
                              void* d_out, int out_size) {
    (void)in_sizes; (void)n_in; (void)out_size;
    const float* x  = (const float*)d_in[0];
    const float* U0 = (const float*)d_in[1];
    const float* V0 = (const float*)d_in[2];
    const float* b0 = (const float*)d_in[3];
    const float* U1 = (const float*)d_in[4];
    const float* V1 = (const float*)d_in[5];
    const float* b1 = (const float*)d_in[6];
    const float* sw = (const float*)d_in[7];
    const float* sb = (const float*)d_in[8];
    float* out = (float*)d_out;

    cudaFuncSetAttribute(lstm_kernel, cudaFuncAttributeMaxDynamicSharedMemorySize, SMEM_DYN);
    init_kernel<<<512, 256>>>();
    conv_w<<<65536, 256>>>(U0, V0, U1, V1);
    lstm_kernel<<<NB, 256, SMEM_DYN>>>(x, b0, b1, sw, sb, out);
}